// round 4
// baseline (speedup 1.0000x reference)
#include <cuda_runtime.h>
#include <cstdint>

#define MAX_NODES 100000
#define FEAT 128

// ---------------- scratch (device globals; no allocation) ----------------
__device__ float g_agg[(size_t)MAX_NODES * 128];
__device__ float g_h  [(size_t)MAX_NODES * 128];
__device__ float g_z  [(size_t)MAX_NODES * 64];
__device__ int   g_dego[MAX_NODES];
__device__ int   g_degi[MAX_NODES];
__device__ float g_ns[MAX_NODES];
__device__ float g_nd[MAX_NODES];

// ---------------- vectorized global reduction (sm_90+) ----------------
__device__ __forceinline__ void red_add_v4(float* addr, float4 v) {
    asm volatile("red.global.add.v4.f32 [%0], {%1,%2,%3,%4};"
                 :: "l"(addr), "f"(v.x), "f"(v.y), "f"(v.z), "f"(v.w)
                 : "memory");
}

// ---------------- degree + norm ----------------
__global__ void deg_kernel(const int* __restrict__ src, const int* __restrict__ dst, int nE) {
    int e = blockIdx.x * blockDim.x + threadIdx.x;
    if (e < nE) {
        atomicAdd(&g_dego[src[e]], 1);
        atomicAdd(&g_degi[dst[e]], 1);
    }
}

__global__ void norm_kernel(int n) {
    int i = blockIdx.x * blockDim.x + threadIdx.x;
    if (i < n) {
        g_ns[i] = rsqrtf(fmaxf((float)g_dego[i], 1.0f));
        g_nd[i] = rsqrtf(fmaxf((float)g_degi[i], 1.0f));
    }
}

// ---------------- SpMM scatter: agg[dst] += norm_src[src] * X[src] ----------------
// 128 features: one warp per edge, float4 per lane.
__global__ void scatter128(const float* __restrict__ X,
                           const int* __restrict__ src, const int* __restrict__ dst,
                           float* __restrict__ agg, int nE) {
    int t = blockIdx.x * blockDim.x + threadIdx.x;
    int e = t >> 5;
    int lane = t & 31;
    if (e >= nE) return;
    int s = __ldg(&src[e]);
    int d = __ldg(&dst[e]);
    float w = __ldg(&g_ns[s]);
    float4 v = ((const float4*)X)[(size_t)s * 32 + lane];
    v.x *= w; v.y *= w; v.z *= w; v.w *= w;
    red_add_v4(agg + (size_t)d * 128 + lane * 4, v);
}

// 64 features: 16 lanes per edge.
__global__ void scatter64(const float* __restrict__ Z,
                          const int* __restrict__ src, const int* __restrict__ dst,
                          float* __restrict__ out, int nE) {
    int t = blockIdx.x * blockDim.x + threadIdx.x;
    int e = t >> 4;
    int l = t & 15;
    if (e >= nE) return;
    int s = __ldg(&src[e]);
    int d = __ldg(&dst[e]);
    float w = __ldg(&g_ns[s]);
    float4 v = ((const float4*)Z)[(size_t)s * 16 + l];
    v.x *= w; v.y *= w; v.z *= w; v.w *= w;
    red_add_v4(out + (size_t)d * 64 + l * 4, v);
}

// ---------------- GEMM: out[M,BN] = epi( (rowscale? diag(nd)*A : A) @ W + bias ) ----------------
// K = 128 fixed. BM = 128, BK = 16, 256 threads, TM = 8.
template <int BN, int TN, bool SCALE, bool BIAS_RELU>
__global__ void gemm_k128(const float* __restrict__ A, const float* __restrict__ W,
                          const float* __restrict__ bias, float* __restrict__ out, int M) {
    __shared__ float As[16][132];      // [k][m], padded
    __shared__ float Bs[16][BN];       // [k][n]

    const int tid = threadIdx.x;
    const int tx = tid & 15;           // 16 cols of threads -> BN via TN
    const int ty = tid >> 4;           // 16 rows of threads -> 128 via TM=8
    const int m0 = blockIdx.x * 128;

    float acc[8][TN];
#pragma unroll
    for (int i = 0; i < 8; i++)
#pragma unroll
        for (int j = 0; j < TN; j++) acc[i][j] = 0.0f;

    for (int kk = 0; kk < 128; kk += 16) {
        // load A tile: 128 rows x 16 cols = 512 float4
#pragma unroll
        for (int j = 0; j < 2; j++) {
            int idx = tid + j * 256;
            int rid = idx >> 2;
            int cid = idx & 3;
            int row = m0 + rid;
            float4 f = make_float4(0.f, 0.f, 0.f, 0.f);
            if (row < M) {
                f = *((const float4*)(A + (size_t)row * 128 + kk + cid * 4));
                if (SCALE) {
                    float rs = __ldg(&g_nd[row]);
                    f.x *= rs; f.y *= rs; f.z *= rs; f.w *= rs;
                }
            }
            As[cid * 4 + 0][rid] = f.x;
            As[cid * 4 + 1][rid] = f.y;
            As[cid * 4 + 2][rid] = f.z;
            As[cid * 4 + 3][rid] = f.w;
        }
        // load B tile: 16 x BN
#pragma unroll
        for (int j = 0; j < BN / 64; j++) {
            int idx = tid + j * 256;
            int kr = idx / (BN / 4);
            int nc = idx % (BN / 4);
            *((float4*)&Bs[kr][nc * 4]) =
                *((const float4*)(W + (size_t)(kk + kr) * BN + nc * 4));
        }
        __syncthreads();

#pragma unroll
        for (int k = 0; k < 16; k++) {
            float a[8];
            *((float4*)(a + 0)) = *((float4*)&As[k][ty * 8 + 0]);
            *((float4*)(a + 4)) = *((float4*)&As[k][ty * 8 + 4]);
            float b[TN];
#pragma unroll
            for (int j4 = 0; j4 < TN / 4; j4++)
                *((float4*)(b + j4 * 4)) = *((float4*)&Bs[k][tx * TN + j4 * 4]);
#pragma unroll
            for (int i = 0; i < 8; i++)
#pragma unroll
                for (int j = 0; j < TN; j++) acc[i][j] += a[i] * b[j];
        }
        __syncthreads();
    }

#pragma unroll
    for (int i = 0; i < 8; i++) {
        int row = m0 + ty * 8 + i;
        if (row >= M) continue;
#pragma unroll
        for (int j4 = 0; j4 < TN / 4; j4++) {
            int col = tx * TN + j4 * 4;
            float4 v;
            v.x = acc[i][j4 * 4 + 0];
            v.y = acc[i][j4 * 4 + 1];
            v.z = acc[i][j4 * 4 + 2];
            v.w = acc[i][j4 * 4 + 3];
            if (BIAS_RELU) {
                v.x = fmaxf(v.x + __ldg(&bias[col + 0]), 0.f);
                v.y = fmaxf(v.y + __ldg(&bias[col + 1]), 0.f);
                v.z = fmaxf(v.z + __ldg(&bias[col + 2]), 0.f);
                v.w = fmaxf(v.w + __ldg(&bias[col + 3]), 0.f);
            }
            *((float4*)(out + (size_t)row * BN + col)) = v;
        }
    }
}

// ---------------- final epilogue: out = out * nd[row] + b2[col] ----------------
__global__ void final_epilogue(float* __restrict__ out, const float* __restrict__ b2, int M) {
    int idx = blockIdx.x * blockDim.x + threadIdx.x;
    if (idx < M * 64) {
        int row = idx >> 6;
        int col = idx & 63;
        out[idx] = out[idx] * g_nd[row] + __ldg(&b2[col]);
    }
}

// ---------------- launch ----------------
extern "C" void kernel_launch(void* const* d_in, const int* in_sizes, int n_in,
                              void* d_out, int out_size) {
    const float* feat = (const float*)d_in[0];
    const int*   src  = (const int*)d_in[1];
    const int*   dst  = (const int*)d_in[2];
    const float* W0   = (const float*)d_in[3];
    const float* b0   = (const float*)d_in[4];
    const float* W1   = (const float*)d_in[5];
    const float* b1   = (const float*)d_in[6];
    const float* W2   = (const float*)d_in[7];
    const float* b2   = (const float*)d_in[8];

    const int nE = in_sizes[1];
    const int M  = in_sizes[0] / FEAT;

    float* out = (float*)d_out;

    void *p_agg, *p_h, *p_z, *p_dego, *p_degi;
    cudaGetSymbolAddress(&p_agg,  g_agg);
    cudaGetSymbolAddress(&p_h,    g_h);
    cudaGetSymbolAddress(&p_z,    g_z);
    cudaGetSymbolAddress(&p_dego, g_dego);
    cudaGetSymbolAddress(&p_degi, g_degi);

    // degrees + norms
    cudaMemsetAsync(p_dego, 0, (size_t)M * sizeof(int), 0);
    cudaMemsetAsync(p_degi, 0, (size_t)M * sizeof(int), 0);
    deg_kernel<<<(nE + 255) / 256, 256>>>(src, dst, nE);
    norm_kernel<<<(M + 255) / 256, 256>>>(M);

    const unsigned sblocks128 = (unsigned)(((size_t)nE * 32 + 255) / 256);
    const unsigned sblocks64  = (unsigned)(((size_t)nE * 16 + 255) / 256);
    const unsigned gblocks    = (unsigned)((M + 127) / 128);

    // Layer 0: agg = A @ (ns*X);  H1 = relu(diag(nd)*agg @ W0 + b0)
    cudaMemsetAsync(p_agg, 0, (size_t)M * 128 * sizeof(float), 0);
    scatter128<<<sblocks128, 256>>>(feat, src, dst, (float*)p_agg, nE);
    gemm_k128<128, 8, true, true><<<gblocks, 256>>>((const float*)p_agg, W0, b0, (float*)p_h, M);

    // Layer 1
    cudaMemsetAsync(p_agg, 0, (size_t)M * 128 * sizeof(float), 0);
    scatter128<<<sblocks128, 256>>>((const float*)p_h, src, dst, (float*)p_agg, nE);
    gemm_k128<128, 8, true, true><<<gblocks, 256>>>((const float*)p_agg, W1, b1, (float*)p_h, M);

    // Layer 2 (reordered: GEMM first on 128->64, then 64-wide scatter)
    gemm_k128<64, 4, false, false><<<gblocks, 256>>>((const float*)p_h, W2, b2, (float*)p_z, M);
    cudaMemsetAsync(out, 0, (size_t)M * 64 * sizeof(float), 0);
    scatter64<<<sblocks64, 256>>>((const float*)p_z, src, dst, out, nE);
    final_epilogue<<<((size_t)M * 64 + 255) / 256, 256>>>(out, b2, M);
}

// round 5
// speedup vs baseline: 1.8015x; 1.8015x over previous
#include <cuda_runtime.h>
#include <cstdint>

#define MAX_NODES 100000
#define MAX_EDGES 1600000
#define FEAT 128

// ---------------- scratch (device globals; no allocation) ----------------
__device__ float g_agg[(size_t)MAX_NODES * 128];
__device__ float g_h  [(size_t)MAX_NODES * 128];
__device__ float g_z  [(size_t)MAX_NODES * 64];
__device__ int   g_dego[MAX_NODES];
__device__ int   g_degi[MAX_NODES];
__device__ float g_ns[MAX_NODES];
__device__ float g_nd[MAX_NODES];
__device__ int   g_off[MAX_NODES];
__device__ int   g_cursor[MAX_NODES];
__device__ int   g_bsum[1024];
__device__ int   g_csrc[MAX_EDGES];

// ---------------- degree + norm ----------------
__global__ void deg_kernel(const int* __restrict__ src, const int* __restrict__ dst, int nE) {
    int e = blockIdx.x * blockDim.x + threadIdx.x;
    if (e < nE) {
        atomicAdd(&g_dego[src[e]], 1);
        atomicAdd(&g_degi[dst[e]], 1);
    }
}

__global__ void norm_kernel(int n) {
    int i = blockIdx.x * blockDim.x + threadIdx.x;
    if (i < n) {
        g_ns[i] = rsqrtf(fmaxf((float)g_dego[i], 1.0f));
        g_nd[i] = rsqrtf(fmaxf((float)g_degi[i], 1.0f));
    }
}

// ---------------- exclusive scan of g_degi -> g_off (3-kernel) ----------------
__global__ void scan_blocks(int n) {
    __shared__ int s[1024];
    int i = blockIdx.x * 1024 + threadIdx.x;
    int v = (i < n) ? g_degi[i] : 0;
    s[threadIdx.x] = v;
    __syncthreads();
#pragma unroll
    for (int o = 1; o < 1024; o <<= 1) {
        int t = (threadIdx.x >= o) ? s[threadIdx.x - o] : 0;
        __syncthreads();
        s[threadIdx.x] += t;
        __syncthreads();
    }
    if (i < n) g_off[i] = s[threadIdx.x] - v;   // exclusive
    if (threadIdx.x == 1023) g_bsum[blockIdx.x] = s[1023];
}

__global__ void scan_sums(int nb) {
    __shared__ int s[1024];
    int v = (threadIdx.x < nb) ? g_bsum[threadIdx.x] : 0;
    s[threadIdx.x] = v;
    __syncthreads();
#pragma unroll
    for (int o = 1; o < 1024; o <<= 1) {
        int t = (threadIdx.x >= o) ? s[threadIdx.x - o] : 0;
        __syncthreads();
        s[threadIdx.x] += t;
        __syncthreads();
    }
    if (threadIdx.x < nb) g_bsum[threadIdx.x] = s[threadIdx.x] - v;  // exclusive
}

__global__ void scan_add(int n) {
    int i = blockIdx.x * blockDim.x + threadIdx.x;
    if (i < n) {
        int o = g_off[i] + g_bsum[i >> 10];
        g_off[i] = o;
        g_cursor[i] = o;
    }
}

// ---------------- CSR build: for each edge, place src into dst's row ----------------
__global__ void build_csr(const int* __restrict__ src, const int* __restrict__ dst, int nE) {
    int e = blockIdx.x * blockDim.x + threadIdx.x;
    if (e < nE) {
        int p = atomicAdd(&g_cursor[dst[e]], 1);
        g_csrc[p] = src[e];
    }
}

// ---------------- pull aggregation: agg[d] = nd[d] * sum_{s in N(d)} ns[s]*X[s] ----------------
// 128 feats: one warp per node, float4 per lane.
__global__ void pull128(const float* __restrict__ X, float* __restrict__ agg, int M, int nE) {
    int t = blockIdx.x * blockDim.x + threadIdx.x;
    int node = t >> 5;
    int lane = t & 31;
    if (node >= M) return;
    int beg = __ldg(&g_off[node]);
    int end = (node + 1 < M) ? __ldg(&g_off[node + 1]) : nE;
    float4 acc = make_float4(0.f, 0.f, 0.f, 0.f);
    const float4* X4 = (const float4*)X;
    for (int e = beg; e < end; e++) {
        int s = __ldg(&g_csrc[e]);
        float w = __ldg(&g_ns[s]);
        float4 v = __ldg(X4 + (size_t)s * 32 + lane);
        acc.x += w * v.x; acc.y += w * v.y; acc.z += w * v.z; acc.w += w * v.w;
    }
    float nd = __ldg(&g_nd[node]);
    acc.x *= nd; acc.y *= nd; acc.z *= nd; acc.w *= nd;
    ((float4*)agg)[(size_t)node * 32 + lane] = acc;
}

// 64 feats, final layer: half-warp per node, fused *nd + b2, writes d_out.
__global__ void pull64_final(const float* __restrict__ Z, const float* __restrict__ b2,
                             float* __restrict__ out, int M, int nE) {
    int t = blockIdx.x * blockDim.x + threadIdx.x;
    int node = t >> 4;
    int l = t & 15;
    if (node >= M) return;
    int beg = __ldg(&g_off[node]);
    int end = (node + 1 < M) ? __ldg(&g_off[node + 1]) : nE;
    float4 acc = make_float4(0.f, 0.f, 0.f, 0.f);
    const float4* Z4 = (const float4*)Z;
    for (int e = beg; e < end; e++) {
        int s = __ldg(&g_csrc[e]);
        float w = __ldg(&g_ns[s]);
        float4 v = __ldg(Z4 + (size_t)s * 16 + l);
        acc.x += w * v.x; acc.y += w * v.y; acc.z += w * v.z; acc.w += w * v.w;
    }
    float nd = __ldg(&g_nd[node]);
    float4 b = __ldg((const float4*)b2 + l);
    acc.x = acc.x * nd + b.x;
    acc.y = acc.y * nd + b.y;
    acc.z = acc.z * nd + b.z;
    acc.w = acc.w * nd + b.w;
    ((float4*)out)[(size_t)node * 16 + l] = acc;
}

// ---------------- GEMM: out[M,BN] = epi( A @ W + bias ), K = 128 ----------------
template <int BN, int TN, bool BIAS_RELU>
__global__ void gemm_k128(const float* __restrict__ A, const float* __restrict__ W,
                          const float* __restrict__ bias, float* __restrict__ out, int M) {
    __shared__ float As[16][132];      // [k][m], padded
    __shared__ float Bs[16][BN];       // [k][n]

    const int tid = threadIdx.x;
    const int tx = tid & 15;
    const int ty = tid >> 4;
    const int m0 = blockIdx.x * 128;

    float acc[8][TN];
#pragma unroll
    for (int i = 0; i < 8; i++)
#pragma unroll
        for (int j = 0; j < TN; j++) acc[i][j] = 0.0f;

    for (int kk = 0; kk < 128; kk += 16) {
#pragma unroll
        for (int j = 0; j < 2; j++) {
            int idx = tid + j * 256;
            int rid = idx >> 2;
            int cid = idx & 3;
            int row = m0 + rid;
            float4 f = make_float4(0.f, 0.f, 0.f, 0.f);
            if (row < M)
                f = *((const float4*)(A + (size_t)row * 128 + kk + cid * 4));
            As[cid * 4 + 0][rid] = f.x;
            As[cid * 4 + 1][rid] = f.y;
            As[cid * 4 + 2][rid] = f.z;
            As[cid * 4 + 3][rid] = f.w;
        }
#pragma unroll
        for (int j = 0; j < BN / 64; j++) {
            int idx = tid + j * 256;
            int kr = idx / (BN / 4);
            int nc = idx % (BN / 4);
            *((float4*)&Bs[kr][nc * 4]) =
                *((const float4*)(W + (size_t)(kk + kr) * BN + nc * 4));
        }
        __syncthreads();

#pragma unroll
        for (int k = 0; k < 16; k++) {
            float a[8];
            *((float4*)(a + 0)) = *((float4*)&As[k][ty * 8 + 0]);
            *((float4*)(a + 4)) = *((float4*)&As[k][ty * 8 + 4]);
            float b[TN];
#pragma unroll
            for (int j4 = 0; j4 < TN / 4; j4++)
                *((float4*)(b + j4 * 4)) = *((float4*)&Bs[k][tx * TN + j4 * 4]);
#pragma unroll
            for (int i = 0; i < 8; i++)
#pragma unroll
                for (int j = 0; j < TN; j++) acc[i][j] += a[i] * b[j];
        }
        __syncthreads();
    }

#pragma unroll
    for (int i = 0; i < 8; i++) {
        int row = m0 + ty * 8 + i;
        if (row >= M) continue;
#pragma unroll
        for (int j4 = 0; j4 < TN / 4; j4++) {
            int col = tx * TN + j4 * 4;
            float4 v;
            v.x = acc[i][j4 * 4 + 0];
            v.y = acc[i][j4 * 4 + 1];
            v.z = acc[i][j4 * 4 + 2];
            v.w = acc[i][j4 * 4 + 3];
            if (BIAS_RELU) {
                v.x = fmaxf(v.x + __ldg(&bias[col + 0]), 0.f);
                v.y = fmaxf(v.y + __ldg(&bias[col + 1]), 0.f);
                v.z = fmaxf(v.z + __ldg(&bias[col + 2]), 0.f);
                v.w = fmaxf(v.w + __ldg(&bias[col + 3]), 0.f);
            }
            *((float4*)(out + (size_t)row * BN + col)) = v;
        }
    }
}

// ---------------- launch ----------------
extern "C" void kernel_launch(void* const* d_in, const int* in_sizes, int n_in,
                              void* d_out, int out_size) {
    const float* feat = (const float*)d_in[0];
    const int*   src  = (const int*)d_in[1];
    const int*   dst  = (const int*)d_in[2];
    const float* W0   = (const float*)d_in[3];
    const float* b0   = (const float*)d_in[4];
    const float* W1   = (const float*)d_in[5];
    const float* b1   = (const float*)d_in[6];
    const float* W2   = (const float*)d_in[7];
    const float* b2   = (const float*)d_in[8];

    const int nE = in_sizes[1];
    const int M  = in_sizes[0] / FEAT;

    float* out = (float*)d_out;

    void *p_agg, *p_h, *p_z, *p_dego, *p_degi;
    cudaGetSymbolAddress(&p_agg,  g_agg);
    cudaGetSymbolAddress(&p_h,    g_h);
    cudaGetSymbolAddress(&p_z,    g_z);
    cudaGetSymbolAddress(&p_dego, g_dego);
    cudaGetSymbolAddress(&p_degi, g_degi);

    // degrees + norms
    cudaMemsetAsync(p_dego, 0, (size_t)M * sizeof(int), 0);
    cudaMemsetAsync(p_degi, 0, (size_t)M * sizeof(int), 0);
    deg_kernel<<<(nE + 255) / 256, 256>>>(src, dst, nE);
    norm_kernel<<<(M + 255) / 256, 256>>>(M);

    // CSR build (once, reused by all 3 layers)
    const int nb = (M + 1023) / 1024;
    scan_blocks<<<nb, 1024>>>(M);
    scan_sums<<<1, 1024>>>(nb);
    scan_add<<<(M + 255) / 256, 256>>>(M);
    build_csr<<<(nE + 255) / 256, 256>>>(src, dst, nE);

    const unsigned pb128 = (unsigned)(((size_t)M * 32 + 255) / 256);
    const unsigned pb64  = (unsigned)(((size_t)M * 16 + 255) / 256);
    const unsigned gblocks = (unsigned)((M + 127) / 128);

    // Layer 0
    pull128<<<pb128, 256>>>(feat, (float*)p_agg, M, nE);
    gemm_k128<128, 8, true><<<gblocks, 256>>>((const float*)p_agg, W0, b0, (float*)p_h, M);

    // Layer 1
    pull128<<<pb128, 256>>>((const float*)p_h, (float*)p_agg, M, nE);
    gemm_k128<128, 8, true><<<gblocks, 256>>>((const float*)p_agg, W1, b1, (float*)p_h, M);

    // Layer 2: GEMM first (128->64), then 64-wide pull fused with final epilogue
    gemm_k128<64, 4, false><<<gblocks, 256>>>((const float*)p_h, W2, b2, (float*)p_z, M);
    pull64_final<<<pb64, 256>>>((const float*)p_z, b2, out, M, nE);
}

// round 6
// speedup vs baseline: 1.8535x; 1.0289x over previous
#include <cuda_runtime.h>
#include <cstdint>

#define MAX_NODES 100000
#define MAX_EDGES 1600000
#define FEAT 128

// ---------------- scratch (device globals; no allocation) ----------------
__device__ float g_agg[(size_t)MAX_NODES * 128];
__device__ float g_h  [(size_t)MAX_NODES * 128];
__device__ float g_z  [(size_t)MAX_NODES * 64];
__device__ int   g_dego[MAX_NODES];
__device__ int   g_degi[MAX_NODES];
__device__ float g_ns[MAX_NODES];
__device__ float g_nd[MAX_NODES];
__device__ int   g_off[MAX_NODES];
__device__ int   g_cursor[MAX_NODES];
__device__ int   g_bsum[1024];
__device__ int   g_csrc[MAX_EDGES];

// ---------------- degree + norm ----------------
__global__ void deg_kernel(const int* __restrict__ src, const int* __restrict__ dst, int nE) {
    int e = blockIdx.x * blockDim.x + threadIdx.x;
    if (e < nE) {
        atomicAdd(&g_dego[src[e]], 1);
        atomicAdd(&g_degi[dst[e]], 1);
    }
}

__global__ void norm_kernel(int n) {
    int i = blockIdx.x * blockDim.x + threadIdx.x;
    if (i < n) {
        g_ns[i] = rsqrtf(fmaxf((float)g_dego[i], 1.0f));
        g_nd[i] = rsqrtf(fmaxf((float)g_degi[i], 1.0f));
    }
}

// ---------------- exclusive scan of g_degi -> g_off ----------------
__global__ void scan_blocks(int n) {
    __shared__ int s[1024];
    int i = blockIdx.x * 1024 + threadIdx.x;
    int v = (i < n) ? g_degi[i] : 0;
    s[threadIdx.x] = v;
    __syncthreads();
#pragma unroll
    for (int o = 1; o < 1024; o <<= 1) {
        int t = (threadIdx.x >= o) ? s[threadIdx.x - o] : 0;
        __syncthreads();
        s[threadIdx.x] += t;
        __syncthreads();
    }
    if (i < n) g_off[i] = s[threadIdx.x] - v;
    if (threadIdx.x == 1023) g_bsum[blockIdx.x] = s[1023];
}

__global__ void scan_sums(int nb) {
    __shared__ int s[1024];
    int v = (threadIdx.x < nb) ? g_bsum[threadIdx.x] : 0;
    s[threadIdx.x] = v;
    __syncthreads();
#pragma unroll
    for (int o = 1; o < 1024; o <<= 1) {
        int t = (threadIdx.x >= o) ? s[threadIdx.x - o] : 0;
        __syncthreads();
        s[threadIdx.x] += t;
        __syncthreads();
    }
    if (threadIdx.x < nb) g_bsum[threadIdx.x] = s[threadIdx.x] - v;
}

__global__ void scan_add(int n) {
    int i = blockIdx.x * blockDim.x + threadIdx.x;
    if (i < n) {
        int o = g_off[i] + g_bsum[i >> 10];
        g_off[i] = o;
        g_cursor[i] = o;
    }
}

__global__ void build_csr(const int* __restrict__ src, const int* __restrict__ dst, int nE) {
    int e = blockIdx.x * blockDim.x + threadIdx.x;
    if (e < nE) {
        int p = atomicAdd(&g_cursor[dst[e]], 1);
        g_csrc[p] = src[e];
    }
}

// ---------------- pull aggregation ----------------
__global__ void pull128(const float* __restrict__ X, float* __restrict__ agg, int M, int nE) {
    int t = blockIdx.x * blockDim.x + threadIdx.x;
    int node = t >> 5;
    int lane = t & 31;
    if (node >= M) return;
    int beg = __ldg(&g_off[node]);
    int end = (node + 1 < M) ? __ldg(&g_off[node + 1]) : nE;
    float4 acc = make_float4(0.f, 0.f, 0.f, 0.f);
    const float4* X4 = (const float4*)X;
    for (int e = beg; e < end; e++) {
        int s = __ldg(&g_csrc[e]);
        float w = __ldg(&g_ns[s]);
        float4 v = __ldg(X4 + (size_t)s * 32 + lane);
        acc.x += w * v.x; acc.y += w * v.y; acc.z += w * v.z; acc.w += w * v.w;
    }
    float nd = __ldg(&g_nd[node]);
    acc.x *= nd; acc.y *= nd; acc.z *= nd; acc.w *= nd;
    ((float4*)agg)[(size_t)node * 32 + lane] = acc;
}

__global__ void pull64_final(const float* __restrict__ Z, const float* __restrict__ b2,
                             float* __restrict__ out, int M, int nE) {
    int t = blockIdx.x * blockDim.x + threadIdx.x;
    int node = t >> 4;
    int l = t & 15;
    if (node >= M) return;
    int beg = __ldg(&g_off[node]);
    int end = (node + 1 < M) ? __ldg(&g_off[node + 1]) : nE;
    float4 acc = make_float4(0.f, 0.f, 0.f, 0.f);
    const float4* Z4 = (const float4*)Z;
    for (int e = beg; e < end; e++) {
        int s = __ldg(&g_csrc[e]);
        float w = __ldg(&g_ns[s]);
        float4 v = __ldg(Z4 + (size_t)s * 16 + l);
        acc.x += w * v.x; acc.y += w * v.y; acc.z += w * v.z; acc.w += w * v.w;
    }
    float nd = __ldg(&g_nd[node]);
    float4 b = __ldg((const float4*)b2 + l);
    acc.x = acc.x * nd + b.x;
    acc.y = acc.y * nd + b.y;
    acc.z = acc.z * nd + b.z;
    acc.w = acc.w * nd + b.w;
    ((float4*)out)[(size_t)node * 16 + l] = acc;
}

// ---------------- tf32 helpers ----------------
__device__ __forceinline__ float f2tf32(float x) {
    uint32_t r;
    asm("cvt.rna.tf32.f32 %0, %1;" : "=r"(r) : "f"(x));
    return __uint_as_float(r);
}

__device__ __forceinline__ void mma_tf32(float* d, const uint32_t* a, const uint32_t* b) {
    asm volatile(
        "mma.sync.aligned.m16n8k8.row.col.f32.tf32.tf32.f32 "
        "{%0,%1,%2,%3}, {%4,%5,%6,%7}, {%8,%9}, {%0,%1,%2,%3};"
        : "+f"(d[0]), "+f"(d[1]), "+f"(d[2]), "+f"(d[3])
        : "r"(a[0]), "r"(a[1]), "r"(a[2]), "r"(a[3]), "r"(b[0]), "r"(b[1]));
}

// ---------------- TF32 tensor-core GEMM (3xTF32 split for fp32 accuracy) ----------------
// out[M,BN] = epi(A[M,128] @ W[128,BN] + bias). BM=128, BK=16, 256 threads.
// Warp grid 4(m) x 2(n); warp tile 32 x (BN/2); mma m16n8k8.
template <int BN, bool RELU>
__global__ void __launch_bounds__(256) gemm_tf32(
    const float* __restrict__ A, const float* __restrict__ W,
    const float* __restrict__ bias, float* __restrict__ out, int M) {

    constexpr int NT = BN / 16;          // n-tiles per warp (8 or 4)
    constexpr int NCH = NT / 4;          // n-chunks of 4 tiles (2 or 1)
    constexpr int AP = 20;               // A smem row stride (pad)
    constexpr int BNP = BN + 8;          // B smem row stride (pad)

    __shared__ float Ah[128 * AP], Al[128 * AP];
    __shared__ float Bh[16 * BNP], Bl[16 * BNP];

    const int tid = threadIdx.x;
    const int lane = tid & 31;
    const int warp = tid >> 5;
    const int wm = warp & 3;             // warp row (0..3) -> m offset wm*32
    const int wn = (warp >> 2) * (BN / 2); // warp col offset (0 or BN/2)
    const int m0 = blockIdx.x * 128;

    float acc[2][NT][4];
#pragma unroll
    for (int mt = 0; mt < 2; mt++)
#pragma unroll
        for (int nt = 0; nt < NT; nt++)
#pragma unroll
            for (int i = 0; i < 4; i++) acc[mt][nt][i] = 0.0f;

    for (int kk = 0; kk < 128; kk += 16) {
        // ---- load A tile 128x16 -> hi/lo smem ----
#pragma unroll
        for (int j = 0; j < 2; j++) {
            int idx = tid + j * 256;
            int rid = idx >> 2;
            int cid = idx & 3;
            int row = m0 + rid;
            float4 v = make_float4(0.f, 0.f, 0.f, 0.f);
            if (row < M)
                v = *((const float4*)(A + (size_t)row * 128 + kk + cid * 4));
            float4 h, l;
            h.x = f2tf32(v.x); l.x = f2tf32(v.x - h.x);
            h.y = f2tf32(v.y); l.y = f2tf32(v.y - h.y);
            h.z = f2tf32(v.z); l.z = f2tf32(v.z - h.z);
            h.w = f2tf32(v.w); l.w = f2tf32(v.w - h.w);
            *((float4*)&Ah[rid * AP + cid * 4]) = h;
            *((float4*)&Al[rid * AP + cid * 4]) = l;
        }
        // ---- load B tile 16xBN -> hi/lo smem ----
#pragma unroll
        for (int j = 0; j < BN / 64; j++) {
            int idx = tid + j * 256;
            int kr = idx / (BN / 4);
            int nc = idx % (BN / 4);
            float4 v = *((const float4*)(W + (size_t)(kk + kr) * BN + nc * 4));
            float4 h, l;
            h.x = f2tf32(v.x); l.x = f2tf32(v.x - h.x);
            h.y = f2tf32(v.y); l.y = f2tf32(v.y - h.y);
            h.z = f2tf32(v.z); l.z = f2tf32(v.z - h.z);
            h.w = f2tf32(v.w); l.w = f2tf32(v.w - h.w);
            *((float4*)&Bh[kr * BNP + nc * 4]) = h;
            *((float4*)&Bl[kr * BNP + nc * 4]) = l;
        }
        __syncthreads();

#pragma unroll
        for (int ks = 0; ks < 2; ks++) {
            const int k0 = ks * 8;
            const int krow = k0 + (lane & 3);
#pragma unroll
            for (int nc = 0; nc < NCH; nc++) {
                uint32_t bh[4][2], bl[4][2];
#pragma unroll
                for (int j = 0; j < 4; j++) {
                    int col = wn + (nc * 4 + j) * 8 + (lane >> 2);
                    bh[j][0] = __float_as_uint(Bh[krow * BNP + col]);
                    bh[j][1] = __float_as_uint(Bh[(krow + 4) * BNP + col]);
                    bl[j][0] = __float_as_uint(Bl[krow * BNP + col]);
                    bl[j][1] = __float_as_uint(Bl[(krow + 4) * BNP + col]);
                }
#pragma unroll
                for (int mt = 0; mt < 2; mt++) {
                    const int r0 = wm * 32 + mt * 16 + (lane >> 2);
                    const int c0 = k0 + (lane & 3);
                    uint32_t ah[4], al[4];
                    ah[0] = __float_as_uint(Ah[r0 * AP + c0]);
                    ah[1] = __float_as_uint(Ah[(r0 + 8) * AP + c0]);
                    ah[2] = __float_as_uint(Ah[r0 * AP + c0 + 4]);
                    ah[3] = __float_as_uint(Ah[(r0 + 8) * AP + c0 + 4]);
                    al[0] = __float_as_uint(Al[r0 * AP + c0]);
                    al[1] = __float_as_uint(Al[(r0 + 8) * AP + c0]);
                    al[2] = __float_as_uint(Al[r0 * AP + c0 + 4]);
                    al[3] = __float_as_uint(Al[(r0 + 8) * AP + c0 + 4]);
#pragma unroll
                    for (int j = 0; j < 4; j++) {
                        int nt = nc * 4 + j;
                        mma_tf32(acc[mt][nt], ah, bh[j]);
                        mma_tf32(acc[mt][nt], ah, bl[j]);
                        mma_tf32(acc[mt][nt], al, bh[j]);
                    }
                }
            }
        }
        __syncthreads();
    }

    // ---- epilogue ----
#pragma unroll
    for (int mt = 0; mt < 2; mt++) {
        const int row0 = m0 + wm * 32 + mt * 16 + (lane >> 2);
#pragma unroll
        for (int nt = 0; nt < NT; nt++) {
            const int col = wn + nt * 8 + 2 * (lane & 3);
#pragma unroll
            for (int h = 0; h < 2; h++) {
                int row = row0 + 8 * h;
                if (row < M) {
                    float2 v;
                    v.x = acc[mt][nt][2 * h + 0];
                    v.y = acc[mt][nt][2 * h + 1];
                    if (RELU) {
                        v.x = fmaxf(v.x + __ldg(&bias[col + 0]), 0.f);
                        v.y = fmaxf(v.y + __ldg(&bias[col + 1]), 0.f);
                    }
                    *((float2*)(out + (size_t)row * BN + col)) = v;
                }
            }
        }
    }
}

// ---------------- launch ----------------
extern "C" void kernel_launch(void* const* d_in, const int* in_sizes, int n_in,
                              void* d_out, int out_size) {
    const float* feat = (const float*)d_in[0];
    const int*   src  = (const int*)d_in[1];
    const int*   dst  = (const int*)d_in[2];
    const float* W0   = (const float*)d_in[3];
    const float* b0   = (const float*)d_in[4];
    const float* W1   = (const float*)d_in[5];
    const float* b1   = (const float*)d_in[6];
    const float* W2   = (const float*)d_in[7];
    const float* b2   = (const float*)d_in[8];

    const int nE = in_sizes[1];
    const int M  = in_sizes[0] / FEAT;

    float* out = (float*)d_out;

    void *p_agg, *p_h, *p_z, *p_dego, *p_degi;
    cudaGetSymbolAddress(&p_agg,  g_agg);
    cudaGetSymbolAddress(&p_h,    g_h);
    cudaGetSymbolAddress(&p_z,    g_z);
    cudaGetSymbolAddress(&p_dego, g_dego);
    cudaGetSymbolAddress(&p_degi, g_degi);

    // degrees + norms
    cudaMemsetAsync(p_dego, 0, (size_t)M * sizeof(int), 0);
    cudaMemsetAsync(p_degi, 0, (size_t)M * sizeof(int), 0);
    deg_kernel<<<(nE + 255) / 256, 256>>>(src, dst, nE);
    norm_kernel<<<(M + 255) / 256, 256>>>(M);

    // CSR build (once, reused by all 3 layers)
    const int nb = (M + 1023) / 1024;
    scan_blocks<<<nb, 1024>>>(M);
    scan_sums<<<1, 1024>>>(nb);
    scan_add<<<(M + 255) / 256, 256>>>(M);
    build_csr<<<(nE + 255) / 256, 256>>>(src, dst, nE);

    const unsigned pb128 = (unsigned)(((size_t)M * 32 + 255) / 256);
    const unsigned pb64  = (unsigned)(((size_t)M * 16 + 255) / 256);
    const unsigned gblocks = (unsigned)((M + 127) / 128);

    // Layer 0
    pull128<<<pb128, 256>>>(feat, (float*)p_agg, M, nE);
    gemm_tf32<128, true><<<gblocks, 256>>>((const float*)p_agg, W0, b0, (float*)p_h, M);

    // Layer 1
    pull128<<<pb128, 256>>>((const float*)p_h, (float*)p_agg, M, nE);
    gemm_tf32<128, true><<<gblocks, 256>>>((const float*)p_agg, W1, b1, (float*)p_h, M);

    // Layer 2: GEMM first (128->64), then 64-wide pull fused with final epilogue
    gemm_tf32<64, false><<<gblocks, 256>>>((const float*)p_h, W2, b2, (float*)p_z, M);
    pull64_final<<<pb64, 256>>>((const float*)p_z, b2, out, M, nE);
}